// round 12
// baseline (speedup 1.0000x reference)
#include <cuda_runtime.h>
#include <math.h>
#include <stdint.h>

#define NB   256   // batch
#define CCH  64    // channels
#define INF  1024  // in features
#define OUTF 1024  // out features

#define BM 128
#define BN 128
#define BK 32
#define SPAD 4
#define TSTRIDE (BK + SPAD)          // 36 floats
#define TILE_F  (BM * TSTRIDE)       // 4608 floats per matrix tile
#define STAGE_BYTES (2 * TILE_F * 4) // A+B per stage = 36864 B
#define NSTAGE 3
#define SMEM_BYTES (NSTAGE * STAGE_BYTES)  // 110592

// Scratch: sorted rows (tf32-pre-rounded), layout [c][n][x].
__device__ float g_sorted[(size_t)CCH * NB * INF];

__device__ __forceinline__ float f2tf(float f) {
    unsigned u;
    asm("cvt.rna.tf32.f32 %0, %1;" : "=r"(u) : "f"(f));
    return __uint_as_float(u);
}
__device__ __forceinline__ unsigned f2tf_u(unsigned u) {
    asm("cvt.rna.tf32.f32 %0, %1;" : "=r"(u) : "f"(__uint_as_float(u)));
    return u;
}

// ===========================================================================
// Sort: one warp per row, 32 elems/thread, fully-templated bitonic network.
// Compare-exchanges written as predicated-FMNMX-friendly ternaries.
// ===========================================================================
template<int K, int J>
__device__ __forceinline__ void bitonic_stage(float (&e)[32], int lane) {
    if constexpr (J >= 32) {
        constexpr int jj = J >> 5;
        const bool up       = ((lane << 5) & K) == 0;
        const bool lower    = (lane & jj) == 0;
        const bool keep_max = (up == lower);
        #pragma unroll
        for (int r = 0; r < 32; r++) {
            float v = __shfl_xor_sync(0xffffffffu, e[r], jj);
            e[r] = keep_max ? fmaxf(e[r], v) : fminf(e[r], v);  // 1 predicated FMNMX
        }
    } else if constexpr (K >= 32) {
        // runtime direction (depends on lane only) -> predicated FMNMX pair
        const bool up = (((lane << 5) & K) == 0);
        #pragma unroll
        for (int r = 0; r < 32; r++) {
            if ((r & J) == 0) {
                const int rr = r | J;
                float a = e[r], b = e[rr];
                e[r]  = up ? fmaxf(a, b) : fminf(a, b);
                e[rr] = up ? fminf(a, b) : fmaxf(a, b);
            }
        }
    } else {
        // compile-time direction
        #pragma unroll
        for (int r = 0; r < 32; r++) {
            if ((r & J) == 0) {
                const int rr = r | J;
                const bool up = ((r & K) == 0);
                float a = e[r], b = e[rr];
                e[r]  = up ? fmaxf(a, b) : fminf(a, b);
                e[rr] = up ? fminf(a, b) : fmaxf(a, b);
            }
        }
    }
}

template<int K, int J>
__device__ __forceinline__ void bitonic_merge(float (&e)[32], int lane) {
    bitonic_stage<K, J>(e, lane);
    if constexpr (J > 1) bitonic_merge<K, (J >> 1)>(e, lane);
}

template<int K>
__device__ __forceinline__ void bitonic_level(float (&e)[32], int lane) {
    bitonic_merge<K, (K >> 1)>(e, lane);
    if constexpr (K < 1024) bitonic_level<(K << 1)>(e, lane);
}

__global__ __launch_bounds__(256) void sort_rows(const float* __restrict__ x) {
    const int warp_global = blockIdx.x * (blockDim.x >> 5) + (threadIdx.x >> 5);
    const int lane = threadIdx.x & 31;
    const int n = warp_global / CCH;
    const int c = warp_global % CCH;

    const float* src = x + ((size_t)n * CCH + c) * INF;

    float e[32];
    {
        const float4* s4 = (const float4*)(src + lane * 32);
        #pragma unroll
        for (int q = 0; q < 8; q++) {
            float4 v = s4[q];
            e[q * 4 + 0] = v.x; e[q * 4 + 1] = v.y;
            e[q * 4 + 2] = v.z; e[q * 4 + 3] = v.w;
        }
    }

    bitonic_level<2>(e, lane);

    float* dst = g_sorted + ((size_t)c * NB + n) * INF + lane * 32;
    {
        float4* d4 = (float4*)dst;
        #pragma unroll
        for (int q = 0; q < 8; q++) {
            float4 v;
            v.x = f2tf(e[q * 4 + 0]); v.y = f2tf(e[q * 4 + 1]);
            v.z = f2tf(e[q * 4 + 2]); v.w = f2tf(e[q * 4 + 3]);
            d4[q] = v;
        }
    }
}

// ===========================================================================
// Per-channel GEMM, tf32 mma.sync m16n8k8, ldmatrix fragment loads,
// cp.async 3-stage pipeline, ONE barrier per K-tile, warp-staggered kk.
// ===========================================================================
__device__ __forceinline__ void mma_tf32(float* d, const unsigned* a, const unsigned* b) {
    asm volatile(
        "mma.sync.aligned.m16n8k8.row.col.f32.tf32.tf32.f32 "
        "{%0,%1,%2,%3}, {%4,%5,%6,%7}, {%8,%9}, {%0,%1,%2,%3};\n"
        : "+f"(d[0]), "+f"(d[1]), "+f"(d[2]), "+f"(d[3])
        : "r"(a[0]), "r"(a[1]), "r"(a[2]), "r"(a[3]),
          "r"(b[0]), "r"(b[1]));
}

#define LDSM_X4(r0, r1, r2, r3, addr)                                          \
    asm volatile("ldmatrix.sync.aligned.m8n8.x4.shared.b16 {%0,%1,%2,%3}, [%4];" \
                 : "=r"(r0), "=r"(r1), "=r"(r2), "=r"(r3) : "r"(addr))

#define CP_ASYNC16(dst, src)                                                   \
    asm volatile("cp.async.cg.shared.global [%0], [%1], 16;\n"                 \
                 :: "r"(dst), "l"(src))

__device__ __forceinline__ uint32_t smem_u32(const void* p) {
    uint32_t a;
    asm("{ .reg .u64 t; cvta.to.shared.u64 t, %1; cvt.u32.u64 %0, t; }" : "=r"(a) : "l"(p));
    return a;
}

__global__ __launch_bounds__(256, 2) void gemm_tf32(const float* __restrict__ Wt,
                                                    const float* __restrict__ bias,
                                                    float* __restrict__ out) {
    extern __shared__ float smem[];

    const int c  = blockIdx.z;
    const int mt = blockIdx.y;   // 0..1
    const int nt = blockIdx.x;   // 0..7

    const float* Aptr = g_sorted + ((size_t)c * NB + (size_t)mt * BM) * INF;
    const float* Bptr = Wt + ((size_t)c * OUTF + (size_t)nt * BN) * INF;

    const int tid  = threadIdx.x;
    const int warp = tid >> 5, lane = tid & 31;
    const int wm = warp >> 2, wn = warp & 3;     // 2 x 4 warp grid
    const int g = lane >> 2, tig = lane & 3;

    float acc[4][4][4];
    #pragma unroll
    for (int mi = 0; mi < 4; mi++)
        #pragma unroll
        for (int ni = 0; ni < 4; ni++)
            #pragma unroll
            for (int q = 0; q < 4; q++) acc[mi][ni][q] = 0.f;

    const uint32_t S_base = smem_u32(smem);        // stage 0, A region
    const int lrow = tid >> 3;          // 0..31
    const int lcol = (tid & 7) << 2;    // 0,4,...,28
    uint32_t st_off[4];
    #pragma unroll
    for (int r = 0; r < 4; r++)
        st_off[r] = (uint32_t)(((lrow + 32 * r) * TSTRIDE + lcol) * 4);

    // ldmatrix per-lane addresses (stage-0 base; add stage byte offset)
    const int a_row = (lane & 7) + ((lane >> 3) & 1) * 8;
    const int a_kq  = (lane >> 4) * 4;
    uint32_t a_addr[4];
    #pragma unroll
    for (int mi = 0; mi < 4; mi++)
        a_addr[mi] = S_base + (uint32_t)(((wm * 64 + mi * 16 + a_row) * TSTRIDE + a_kq) * 4);
    const int b_q   = lane >> 3;
    const int b_row = (lane & 7) + (b_q >> 1) * 8;
    const int b_kq  = (b_q & 1) * 4;
    uint32_t b_addr[2];
    #pragma unroll
    for (int nj = 0; nj < 2; nj++)
        b_addr[nj] = S_base + (uint32_t)(TILE_F * 4) +
                     (uint32_t)(((wn * 32 + nj * 16 + b_row) * TSTRIDE + b_kq) * 4);

#define ISSUE_LOADS(t, stage)                                                  \
    {                                                                          \
        const float* Ak = Aptr + (t) * BK + lcol;                              \
        const float* Bk = Bptr + (t) * BK + lcol;                              \
        const uint32_t ab = S_base + (uint32_t)(stage) * STAGE_BYTES;          \
        const uint32_t bb = ab + (uint32_t)(TILE_F * 4);                       \
        _Pragma("unroll")                                                      \
        for (int r = 0; r < 4; r++) {                                          \
            CP_ASYNC16(ab + st_off[r], Ak + (size_t)(lrow + 32 * r) * INF);    \
            CP_ASYNC16(bb + st_off[r], Bk + (size_t)(lrow + 32 * r) * INF);    \
        }                                                                      \
    }

    // ---- prologue: stages 0 and 1 in flight ----
    ISSUE_LOADS(0, 0);
    asm volatile("cp.async.commit_group;\n" ::: "memory");
    ISSUE_LOADS(1, 1);
    asm volatile("cp.async.commit_group;\n" ::: "memory");

    const int NT = INF / BK;   // 32
    int st = 0;                // stage holding tile t
    for (int t = 0; t < NT; t++) {
        asm volatile("cp.async.wait_group 1;\n" ::: "memory");  // tile t arrived
        __syncthreads();   // data visible to all; all warps done with MMA(t-1)

        // issue loads for tile t+2 into the stage MMA(t-1) just freed
        if (t + 2 < NT) {
            int ls = st + 2; if (ls >= NSTAGE) ls -= NSTAGE;
            ISSUE_LOADS(t + 2, ls);
        }
        asm volatile("cp.async.commit_group;\n" ::: "memory");

        const uint32_t soff = (uint32_t)st * STAGE_BYTES;
        // warp-staggered slab order: decorrelates LDSM bursts vs MMA bursts
        #pragma unroll
        for (int kx = 0; kx < 4; kx++) {
            const int kk = (kx + warp) & 3;
            const uint32_t koff = soff + (uint32_t)(kk * 8 * 4);
            unsigned a[4][4], b[4][2];
            #pragma unroll
            for (int mi = 0; mi < 4; mi++)
                LDSM_X4(a[mi][0], a[mi][1], a[mi][2], a[mi][3], a_addr[mi] + koff);
            LDSM_X4(b[0][0], b[0][1], b[1][0], b[1][1], b_addr[0] + koff);
            LDSM_X4(b[2][0], b[2][1], b[3][0], b[3][1], b_addr[1] + koff);
            // B loaded raw fp32 -> round to tf32 in registers (rna)
            #pragma unroll
            for (int ni = 0; ni < 4; ni++) {
                b[ni][0] = f2tf_u(b[ni][0]);
                b[ni][1] = f2tf_u(b[ni][1]);
            }
            #pragma unroll
            for (int mi = 0; mi < 4; mi++)
                #pragma unroll
                for (int ni = 0; ni < 4; ni++)
                    mma_tf32(acc[mi][ni], a[mi], b[ni]);
        }

        st++; if (st == NSTAGE) st = 0;
    }

    // epilogue: bias + sigmoid, scatter to out[n][c][o]
    #pragma unroll
    for (int mi = 0; mi < 4; mi++) {
        const int m0 = mt * BM + wm * 64 + mi * 16;
        const int r0 = m0 + g, r1 = m0 + g + 8;
        #pragma unroll
        for (int ni = 0; ni < 4; ni++) {
            const int o0 = nt * BN + wn * 32 + ni * 8 + 2 * tig;
            const float bv0 = __ldg(bias + c * OUTF + o0);
            const float bv1 = __ldg(bias + c * OUTF + o0 + 1);
            float v00 = acc[mi][ni][0] + bv0;
            float v01 = acc[mi][ni][1] + bv1;
            float v10 = acc[mi][ni][2] + bv0;
            float v11 = acc[mi][ni][3] + bv1;
            out[((size_t)r0 * CCH + c) * OUTF + o0    ] = 1.f / (1.f + __expf(-v00));
            out[((size_t)r0 * CCH + c) * OUTF + o0 + 1] = 1.f / (1.f + __expf(-v01));
            out[((size_t)r1 * CCH + c) * OUTF + o0    ] = 1.f / (1.f + __expf(-v10));
            out[((size_t)r1 * CCH + c) * OUTF + o0 + 1] = 1.f / (1.f + __expf(-v11));
        }
    }
}

extern "C" void kernel_launch(void* const* d_in, const int* in_sizes, int n_in,
                              void* d_out, int out_size) {
    const float* x  = (const float*)d_in[0];
    const float* Wt = (const float*)d_in[1];
    const float* b  = (const float*)d_in[2];
    float* out = (float*)d_out;

    sort_rows<<<(NB * CCH) / 8, 256>>>(x);

    static bool attr_set = false;
    if (!attr_set) {
        cudaFuncSetAttribute(gemm_tf32, cudaFuncAttributeMaxDynamicSharedMemorySize,
                             SMEM_BYTES);
        attr_set = true;
    }

    dim3 grid(OUTF / BN, NB / BM, CCH);
    gemm_tf32<<<grid, 256, SMEM_BYTES>>>(Wt, b, out);
}